// round 8
// baseline (speedup 1.0000x reference)
#include <cuda_runtime.h>
#include <cstdint>

#define N_NODES 50000
#define D 128
#define DOUT 64
#define E_EDGES 800000

#define SCAN_BLK 2048
#define SCAN_GRID 25            // blocks 0..24 handle the scan
#define CSR_BLOCKS 148          // <= SM count: all blocks co-resident, barriers safe
#define CSR_THREADS (CSR_BLOCKS * 256)

// ---------------- device globals (no allocation allowed) ----------------
__device__ __align__(16) float g_agg1[N_NODES * D];
__device__ __align__(16) float g_h2[N_NODES * DOUT];
__device__ __align__(16) float g_bc[D];
// g_rowcnt[0..N) = histogram; [N..N+3) = barrier counters; [N+3..N+6) = flags
__device__ int g_rowcnt[N_NODES + 8];
__device__ int g_rowptr[N_NODES + 1];
__device__ int g_cursor[N_NODES];
__device__ int g_csr_src[E_EDGES];
__device__ int g_blocksum[SCAN_GRID];
// tf32 split weight images, transposed: [out_col][k]
__device__ __align__(16) float g_WcT_h[D * D];
__device__ __align__(16) float g_WcT_l[D * D];
__device__ __align__(16) float g_W2T_h[DOUT * D];
__device__ __align__(16) float g_W2T_l[DOUT * D];

// ---------------- tf32 helpers ----------------
__device__ __forceinline__ uint32_t f2tf32(float f) {
    uint32_t r;
    asm("cvt.rna.tf32.f32 %0, %1;" : "=r"(r) : "f"(f));
    return r;
}

__device__ __forceinline__ void split_tf32(float a, uint32_t& hi, uint32_t& lo) {
    hi = f2tf32(a);
    lo = f2tf32(a - __uint_as_float(hi));
}

__device__ __forceinline__ void mma_tf32(float* d, const uint32_t* a,
                                         uint32_t b0, uint32_t b1) {
    asm volatile(
        "mma.sync.aligned.m16n8k8.row.col.f32.tf32.tf32.f32 "
        "{%0,%1,%2,%3}, {%4,%5,%6,%7}, {%8,%9}, {%0,%1,%2,%3};"
        : "+f"(d[0]), "+f"(d[1]), "+f"(d[2]), "+f"(d[3])
        : "r"(a[0]), "r"(a[1]), "r"(a[2]), "r"(a[3]), "r"(b0), "r"(b1));
}

// ---------------- grid barrier (all CSR_BLOCKS co-resident) ----------------
__device__ __forceinline__ void gridbar(int k) {
    __syncthreads();
    if (threadIdx.x == 0) {
        int t = atomicAdd(&g_rowcnt[N_NODES + k], 1);
        if (t == CSR_BLOCKS - 1) {
            __threadfence();
            ((volatile int*)g_rowcnt)[N_NODES + 3 + k] = 1;
        } else {
            while (((volatile int*)g_rowcnt)[N_NODES + 3 + k] == 0) {}
            __threadfence();
        }
    }
    __syncthreads();
}

// ---------------------------------------------------------------------------
// Single persistent CSR-build kernel: prep + hist | scan1 | scan3 | fill
// ---------------------------------------------------------------------------
__global__ void __launch_bounds__(256) csr_kernel(
    const int* __restrict__ src, const int* __restrict__ dst,
    const float* __restrict__ W_pre, const float* __restrict__ b_pre,
    const float* __restrict__ W1, const float* __restrict__ b1,
    const float* __restrict__ W2)
{
    __shared__ int sh[9];
    int tid = threadIdx.x;
    int bid = blockIdx.x;
    int gid = bid * 256 + tid;

    // ---- phase 1a: weight prep (first (D+1+DOUT)*D threads) ----
    if (gid < (D + 1 + DOUT) * D) {
        int r = gid >> 7;
        int c = gid & 127;
        if (r < D) {
            float acc = 0.f;
#pragma unroll 8
            for (int k = 0; k < D; k++) acc += W_pre[r * D + k] * W1[k * D + c];
            uint32_t hi, lo;
            split_tf32(acc, hi, lo);
            g_WcT_h[c * D + r] = __uint_as_float(hi);
            g_WcT_l[c * D + r] = __uint_as_float(lo);
        } else if (r == D) {
            float acc = b1[c];
#pragma unroll 8
            for (int k = 0; k < D; k++) acc += b_pre[k] * W1[k * D + c];
            g_bc[c] = acc;
        } else {
            int n = r - D - 1;
            uint32_t hi, lo;
            split_tf32(W2[c * DOUT + n], hi, lo);
            g_W2T_h[n * D + c] = __uint_as_float(hi);
            g_W2T_l[n * D + c] = __uint_as_float(lo);
        }
    }

    // ---- phase 1b: histogram (grid-stride) ----
    for (int e = gid; e < E_EDGES; e += CSR_THREADS)
        atomicAdd(&g_rowcnt[dst[e]], 1);

    gridbar(0);

    // ---- phase 2: block-local exclusive scan (blocks 0..24) ----
    if (bid < SCAN_GRID) {
        int lane = tid & 31, warp = tid >> 5;
        int base = bid * SCAN_BLK + tid * 8;
        int v[8], s = 0;
#pragma unroll
        for (int j = 0; j < 8; j++) {
            int i = base + j;
            v[j] = (i < N_NODES) ? g_rowcnt[i] : 0;
            s += v[j];
        }
        int ps = s;
#pragma unroll
        for (int off = 1; off < 32; off <<= 1) {
            int n = __shfl_up_sync(0xffffffffu, ps, off);
            if (lane >= off) ps += n;
        }
        if (lane == 31) sh[warp] = ps;
        __syncthreads();
        if (warp == 0 && lane < 8) {
            int ws = sh[lane];
#pragma unroll
            for (int off = 1; off < 8; off <<= 1) {
                int n = __shfl_up_sync(0x000000ffu, ws, off);
                if (lane >= off) ws += n;
            }
            sh[lane] = ws;
        }
        __syncthreads();
        int woff = (warp == 0) ? 0 : sh[warp - 1];
        int run = ps - s + woff;
#pragma unroll
        for (int j = 0; j < 8; j++) {
            int i = base + j;
            if (i < N_NODES) g_rowptr[i] = run;
            run += v[j];
        }
        if (tid == 255) g_blocksum[bid] = run;
    }

    gridbar(1);

    // ---- phase 3: add block offsets, seed cursor (blocks 0..24) ----
    if (bid < SCAN_GRID) {
        if (tid < 32) {
            int lane = tid;
            int v = (lane < SCAN_GRID) ? g_blocksum[lane] : 0;
            int ps = v;
#pragma unroll
            for (int off = 1; off < 32; off <<= 1) {
                int n = __shfl_up_sync(0xffffffffu, ps, off);
                if (lane >= off) ps += n;
            }
            if (lane == bid) sh[8] = ps - v;
            if (bid == SCAN_GRID - 1 && lane == SCAN_GRID - 1)
                g_rowptr[N_NODES] = ps;
        }
        __syncthreads();
        int off = sh[8];
        int base = bid * SCAN_BLK + tid * 8;
#pragma unroll
        for (int j = 0; j < 8; j++) {
            int i = base + j;
            if (i < N_NODES) {
                int p = g_rowptr[i] + off;
                g_rowptr[i] = p;
                g_cursor[i] = p;
            }
        }
    }

    gridbar(2);

    // ---- phase 4: fill (grid-stride) ----
    for (int e = gid; e < E_EDGES; e += CSR_THREADS) {
        int pos = atomicAdd(&g_cursor[dst[e]], 1);
        g_csr_src[pos] = src[e];
    }
}

// ---------------------------------------------------------------------------
// Gather layer 1 (fp32, 128 dims, warp per node) — 4x unrolled
// ---------------------------------------------------------------------------
__global__ void gather1_kernel(const float* __restrict__ x) {
    int node = (blockIdx.x * blockDim.x + threadIdx.x) >> 5;
    int lane = threadIdx.x & 31;
    if (node >= N_NODES) return;
    int beg = g_rowptr[node];
    int end = g_rowptr[node + 1];

    float4 acc = *reinterpret_cast<const float4*>(x + (size_t)node * D + lane * 4);

    for (int base = beg; base < end; base += 32) {
        int idx = 0;
        if (base + lane < end) idx = __ldg(&g_csr_src[base + lane]);
        int m = end - base; if (m > 32) m = 32;
        int j = 0;
        for (; j + 4 <= m; j += 4) {
            int s0 = __shfl_sync(0xffffffffu, idx, j);
            int s1 = __shfl_sync(0xffffffffu, idx, j + 1);
            int s2 = __shfl_sync(0xffffffffu, idx, j + 2);
            int s3 = __shfl_sync(0xffffffffu, idx, j + 3);
            float4 v0 = *reinterpret_cast<const float4*>(x + (size_t)s0 * D + lane * 4);
            float4 v1 = *reinterpret_cast<const float4*>(x + (size_t)s1 * D + lane * 4);
            float4 v2 = *reinterpret_cast<const float4*>(x + (size_t)s2 * D + lane * 4);
            float4 v3 = *reinterpret_cast<const float4*>(x + (size_t)s3 * D + lane * 4);
            acc.x += (v0.x + v1.x) + (v2.x + v3.x);
            acc.y += (v0.y + v1.y) + (v2.y + v3.y);
            acc.z += (v0.z + v1.z) + (v2.z + v3.z);
            acc.w += (v0.w + v1.w) + (v2.w + v3.w);
        }
        for (; j < m; j++) {
            int s = __shfl_sync(0xffffffffu, idx, j);
            float4 v = *reinterpret_cast<const float4*>(x + (size_t)s * D + lane * 4);
            acc.x += v.x; acc.y += v.y; acc.z += v.z; acc.w += v.w;
        }
    }
    float inv = 1.0f / (float)(end - beg + 1);
    acc.x *= inv; acc.y *= inv; acc.z *= inv; acc.w *= inv;
    *reinterpret_cast<float4*>(g_agg1 + (size_t)node * D + lane * 4) = acc;
}

// ---------------------------------------------------------------------------
// Fused GEMM via mma.sync tf32 (3xTF32 split), 512 threads / 128-row tile
// ---------------------------------------------------------------------------
#define ASTR 132
#define FG_SMEM ((D + 128 * ASTR + 2 * 128 * ASTR) * 4)

__global__ void __launch_bounds__(512, 1) fusedgemm_kernel() {
    extern __shared__ float sm[];
    float* bias = sm;
    float* sA   = sm + D;
    float* sWh  = sA + 128 * ASTR;
    float* sWl  = sWh + 128 * ASTR;

    int tid = threadIdx.x;
    int w = tid >> 5, lane = tid & 31;
    int g = lane >> 2, qi = lane & 3;
    int row0 = blockIdx.x * 128;

    if (tid < D) bias[tid] = g_bc[tid];
    for (int i = tid; i < 128 * 32; i += 512) {
        int r = i >> 5, c4 = (i & 31) << 2;
        float4 v = make_float4(0.f, 0.f, 0.f, 0.f);
        int row = row0 + r;
        if (row < N_NODES) v = *reinterpret_cast<const float4*>(g_agg1 + (size_t)row * D + c4);
        *reinterpret_cast<float4*>(&sA[r * ASTR + c4]) = v;
    }
    for (int i = tid; i < 128 * 32; i += 512) {
        int r = i >> 5, c4 = (i & 31) << 2;
        *reinterpret_cast<float4*>(&sWh[r * ASTR + c4]) =
            *reinterpret_cast<const float4*>(&g_WcT_h[r * D + c4]);
        *reinterpret_cast<float4*>(&sWl[r * ASTR + c4]) =
            *reinterpret_cast<const float4*>(&g_WcT_l[r * D + c4]);
    }
    __syncthreads();

    int rw0 = (w >> 2) * 32;
    int cw0 = (w & 3) * 32;
    float acc[2][4][4];
#pragma unroll
    for (int mt = 0; mt < 2; mt++)
#pragma unroll
        for (int nt = 0; nt < 4; nt++)
#pragma unroll
            for (int j = 0; j < 4; j++) acc[mt][nt][j] = 0.f;

#pragma unroll 4
    for (int ks = 0; ks < 16; ks++) {
        int k0 = ks * 8;
        uint32_t ah[2][4], al[2][4];
#pragma unroll
        for (int mt = 0; mt < 2; mt++) {
            int rb = rw0 + mt * 16;
            float f0 = sA[(rb + g) * ASTR + k0 + qi];
            float f1 = sA[(rb + g + 8) * ASTR + k0 + qi];
            float f2 = sA[(rb + g) * ASTR + k0 + qi + 4];
            float f3 = sA[(rb + g + 8) * ASTR + k0 + qi + 4];
            split_tf32(f0, ah[mt][0], al[mt][0]);
            split_tf32(f1, ah[mt][1], al[mt][1]);
            split_tf32(f2, ah[mt][2], al[mt][2]);
            split_tf32(f3, ah[mt][3], al[mt][3]);
        }
#pragma unroll
        for (int nt = 0; nt < 4; nt++) {
            int nb = cw0 + nt * 8;
            uint32_t bh0 = __float_as_uint(sWh[(nb + g) * ASTR + k0 + qi]);
            uint32_t bh1 = __float_as_uint(sWh[(nb + g) * ASTR + k0 + qi + 4]);
            uint32_t bl0 = __float_as_uint(sWl[(nb + g) * ASTR + k0 + qi]);
            uint32_t bl1 = __float_as_uint(sWl[(nb + g) * ASTR + k0 + qi + 4]);
#pragma unroll
            for (int mt = 0; mt < 2; mt++) {
                mma_tf32(acc[mt][nt], ah[mt], bh0, bh1);
                mma_tf32(acc[mt][nt], ah[mt], bl0, bl1);
                mma_tf32(acc[mt][nt], al[mt], bh0, bh1);
            }
        }
    }
    __syncthreads();

#pragma unroll
    for (int mt = 0; mt < 2; mt++) {
        int rb = rw0 + mt * 16;
#pragma unroll
        for (int nt = 0; nt < 4; nt++) {
            int c0 = cw0 + nt * 8 + qi * 2;
            float b0 = bias[c0], b1 = bias[c0 + 1];
            sA[(rb + g) * ASTR + c0]         = fmaxf(acc[mt][nt][0] + b0, 0.f);
            sA[(rb + g) * ASTR + c0 + 1]     = fmaxf(acc[mt][nt][1] + b1, 0.f);
            sA[(rb + g + 8) * ASTR + c0]     = fmaxf(acc[mt][nt][2] + b0, 0.f);
            sA[(rb + g + 8) * ASTR + c0 + 1] = fmaxf(acc[mt][nt][3] + b1, 0.f);
        }
    }
    __syncthreads();

    float* sW2h = sWh;
    float* sW2l = sWh + DOUT * ASTR;
    for (int i = tid; i < DOUT * 32; i += 512) {
        int r = i >> 5, c4 = (i & 31) << 2;
        *reinterpret_cast<float4*>(&sW2h[r * ASTR + c4]) =
            *reinterpret_cast<const float4*>(&g_W2T_h[r * D + c4]);
        *reinterpret_cast<float4*>(&sW2l[r * ASTR + c4]) =
            *reinterpret_cast<const float4*>(&g_W2T_l[r * D + c4]);
    }
    __syncthreads();

    int cw2 = (w & 3) * 16;
    float acc2[2][2][4];
#pragma unroll
    for (int mt = 0; mt < 2; mt++)
#pragma unroll
        for (int nt = 0; nt < 2; nt++)
#pragma unroll
            for (int j = 0; j < 4; j++) acc2[mt][nt][j] = 0.f;

#pragma unroll 4
    for (int ks = 0; ks < 16; ks++) {
        int k0 = ks * 8;
        uint32_t ah[2][4], al[2][4];
#pragma unroll
        for (int mt = 0; mt < 2; mt++) {
            int rb = rw0 + mt * 16;
            float f0 = sA[(rb + g) * ASTR + k0 + qi];
            float f1 = sA[(rb + g + 8) * ASTR + k0 + qi];
            float f2 = sA[(rb + g) * ASTR + k0 + qi + 4];
            float f3 = sA[(rb + g + 8) * ASTR + k0 + qi + 4];
            split_tf32(f0, ah[mt][0], al[mt][0]);
            split_tf32(f1, ah[mt][1], al[mt][1]);
            split_tf32(f2, ah[mt][2], al[mt][2]);
            split_tf32(f3, ah[mt][3], al[mt][3]);
        }
#pragma unroll
        for (int nt = 0; nt < 2; nt++) {
            int nb = cw2 + nt * 8;
            uint32_t bh0 = __float_as_uint(sW2h[(nb + g) * ASTR + k0 + qi]);
            uint32_t bh1 = __float_as_uint(sW2h[(nb + g) * ASTR + k0 + qi + 4]);
            uint32_t bl0 = __float_as_uint(sW2l[(nb + g) * ASTR + k0 + qi]);
            uint32_t bl1 = __float_as_uint(sW2l[(nb + g) * ASTR + k0 + qi + 4]);
#pragma unroll
            for (int mt = 0; mt < 2; mt++) {
                mma_tf32(acc2[mt][nt], ah[mt], bh0, bh1);
                mma_tf32(acc2[mt][nt], ah[mt], bl0, bl1);
                mma_tf32(acc2[mt][nt], al[mt], bh0, bh1);
            }
        }
    }
    __syncthreads();

    float* h2s = sA;
#pragma unroll
    for (int mt = 0; mt < 2; mt++) {
        int rb = rw0 + mt * 16;
#pragma unroll
        for (int nt = 0; nt < 2; nt++) {
            int c0 = cw2 + nt * 8 + qi * 2;
            h2s[(rb + g) * 66 + c0]         = acc2[mt][nt][0];
            h2s[(rb + g) * 66 + c0 + 1]     = acc2[mt][nt][1];
            h2s[(rb + g + 8) * 66 + c0]     = acc2[mt][nt][2];
            h2s[(rb + g + 8) * 66 + c0 + 1] = acc2[mt][nt][3];
        }
    }
    __syncthreads();
    for (int i = tid; i < 128 * 32; i += 512) {
        int r = i >> 5, c2 = (i & 31) << 1;
        int row = row0 + r;
        if (row < N_NODES) {
            float2 v = *reinterpret_cast<const float2*>(&h2s[r * 66 + c2]);
            *reinterpret_cast<float2*>(&g_h2[(size_t)row * DOUT + c2]) = v;
        }
    }
}

// ---------------------------------------------------------------------------
// Gather layer 2 + bias + L2 normalize, fused (64 dims) — 4x unrolled
// ---------------------------------------------------------------------------
__global__ void gather2_kernel(const float* __restrict__ b2,
                               float* __restrict__ out) {
    int node = (blockIdx.x * blockDim.x + threadIdx.x) >> 5;
    int lane = threadIdx.x & 31;
    if (node >= N_NODES) return;
    int beg = g_rowptr[node];
    int end = g_rowptr[node + 1];

    float2 acc = *reinterpret_cast<const float2*>(g_h2 + (size_t)node * DOUT + lane * 2);

    for (int base = beg; base < end; base += 32) {
        int idx = 0;
        if (base + lane < end) idx = __ldg(&g_csr_src[base + lane]);
        int m = end - base; if (m > 32) m = 32;
        int j = 0;
        for (; j + 4 <= m; j += 4) {
            int s0 = __shfl_sync(0xffffffffu, idx, j);
            int s1 = __shfl_sync(0xffffffffu, idx, j + 1);
            int s2 = __shfl_sync(0xffffffffu, idx, j + 2);
            int s3 = __shfl_sync(0xffffffffu, idx, j + 3);
            float2 v0 = *reinterpret_cast<const float2*>(g_h2 + (size_t)s0 * DOUT + lane * 2);
            float2 v1 = *reinterpret_cast<const float2*>(g_h2 + (size_t)s1 * DOUT + lane * 2);
            float2 v2 = *reinterpret_cast<const float2*>(g_h2 + (size_t)s2 * DOUT + lane * 2);
            float2 v3 = *reinterpret_cast<const float2*>(g_h2 + (size_t)s3 * DOUT + lane * 2);
            acc.x += (v0.x + v1.x) + (v2.x + v3.x);
            acc.y += (v0.y + v1.y) + (v2.y + v3.y);
        }
        for (; j < m; j++) {
            int s = __shfl_sync(0xffffffffu, idx, j);
            float2 v = *reinterpret_cast<const float2*>(g_h2 + (size_t)s * DOUT + lane * 2);
            acc.x += v.x; acc.y += v.y;
        }
    }
    float inv = 1.0f / (float)(end - beg + 1);
    float2 b = *reinterpret_cast<const float2*>(b2 + lane * 2);
    float a0 = acc.x * inv + b.x;
    float a1 = acc.y * inv + b.y;
    float ss = a0 * a0 + a1 * a1;
#pragma unroll
    for (int o = 16; o; o >>= 1) ss += __shfl_xor_sync(0xffffffffu, ss, o);
    float s = 1.0f / fmaxf(sqrtf(ss), 1e-12f);
    float2 o2 = make_float2(a0 * s, a1 * s);
    *reinterpret_cast<float2*>(&out[(size_t)node * DOUT + lane * 2]) = o2;
}

// ---------------------------------------------------------------------------
extern "C" void kernel_launch(void* const* d_in, const int* in_sizes, int n_in,
                              void* d_out, int out_size) {
    const float* x     = (const float*)d_in[0];
    const int*   ei    = (const int*)d_in[1];
    const float* W_pre = (const float*)d_in[2];
    const float* b_pre = (const float*)d_in[3];
    const float* W1    = (const float*)d_in[4];
    const float* b1    = (const float*)d_in[5];
    const float* W2    = (const float*)d_in[6];
    const float* b2    = (const float*)d_in[7];
    float* out = (float*)d_out;

    const int* src = ei;
    const int* dst = ei + E_EDGES;

    static void* rowcnt_ptr = nullptr;
    static bool attr_set = false;
    if (!attr_set) {
        cudaFuncSetAttribute(fusedgemm_kernel,
                             cudaFuncAttributeMaxDynamicSharedMemorySize, FG_SMEM);
        cudaGetSymbolAddress(&rowcnt_ptr, g_rowcnt);
        attr_set = true;
    }

    cudaMemsetAsync(rowcnt_ptr, 0, (N_NODES + 8) * sizeof(int));
    csr_kernel<<<CSR_BLOCKS, 256>>>(src, dst, W_pre, b_pre, W1, b1, W2);
    gather1_kernel<<<(N_NODES * 32 + 255) / 256, 256>>>(x);
    fusedgemm_kernel<<<(N_NODES + 127) / 128, 512, FG_SMEM>>>();
    gather2_kernel<<<(N_NODES * 32 + 255) / 256, 256>>>(b2, out);
}

// round 9
// speedup vs baseline: 1.4604x; 1.4604x over previous
#include <cuda_runtime.h>
#include <cstdint>

#define N_NODES 50000
#define D 128
#define DOUT 64
#define E_EDGES 800000

#define SCAN_BLK 2048
#define SCAN_GRID 25   // 25 blocks, co-resident by construction

// ---------------- device globals (no allocation allowed) ----------------
__device__ __align__(16) float g_agg1[N_NODES * D];
__device__ __align__(16) float g_h2[N_NODES * DOUT];
__device__ __align__(16) float g_bc[D];
// [0..N) = histogram; [N..N+8) = barrier counter/flag scratch
__device__ int g_rowcnt[N_NODES + 8];
__device__ int g_rowptr[N_NODES + 1];
__device__ int g_cursor[N_NODES];
__device__ int g_csr_src[E_EDGES];
__device__ int g_blocksum[SCAN_GRID];
// tf32 split weight images, transposed: [out_col][k]
__device__ __align__(16) float g_WcT_h[D * D];
__device__ __align__(16) float g_WcT_l[D * D];
__device__ __align__(16) float g_W2T_h[DOUT * D];
__device__ __align__(16) float g_W2T_l[DOUT * D];

// ---------------- tf32 helpers ----------------
__device__ __forceinline__ uint32_t f2tf32(float f) {
    uint32_t r;
    asm("cvt.rna.tf32.f32 %0, %1;" : "=r"(r) : "f"(f));
    return r;
}

__device__ __forceinline__ void split_tf32(float a, uint32_t& hi, uint32_t& lo) {
    hi = f2tf32(a);
    lo = f2tf32(a - __uint_as_float(hi));
}

__device__ __forceinline__ void mma_tf32(float* d, const uint32_t* a,
                                         uint32_t b0, uint32_t b1) {
    asm volatile(
        "mma.sync.aligned.m16n8k8.row.col.f32.tf32.tf32.f32 "
        "{%0,%1,%2,%3}, {%4,%5,%6,%7}, {%8,%9}, {%0,%1,%2,%3};"
        : "+f"(d[0]), "+f"(d[1]), "+f"(d[2]), "+f"(d[3])
        : "r"(a[0]), "r"(a[1]), "r"(a[2]), "r"(a[3]), "r"(b0), "r"(b1));
}

// ---------------------------------------------------------------------------
// Merged prep (round-7 version)
// ---------------------------------------------------------------------------
__global__ void prep_kernel(const float* __restrict__ W_pre,
                            const float* __restrict__ b_pre,
                            const float* __restrict__ W1,
                            const float* __restrict__ b1,
                            const float* __restrict__ W2) {
    int c = threadIdx.x;
    int r = blockIdx.x;
    if (r < D) {
        float acc = 0.f;
#pragma unroll 8
        for (int k = 0; k < D; k++) acc += W_pre[r * D + k] * W1[k * D + c];
        uint32_t hi, lo;
        split_tf32(acc, hi, lo);
        g_WcT_h[c * D + r] = __uint_as_float(hi);
        g_WcT_l[c * D + r] = __uint_as_float(lo);
    } else if (r == D) {
        float acc = b1[c];
#pragma unroll 8
        for (int k = 0; k < D; k++) acc += b_pre[k] * W1[k * D + c];
        g_bc[c] = acc;
    } else {
        int n = r - D - 1;
        uint32_t hi, lo;
        split_tf32(W2[c * DOUT + n], hi, lo);
        g_W2T_h[n * D + c] = __uint_as_float(hi);
        g_W2T_l[n * D + c] = __uint_as_float(lo);
    }
}

// ---------------------------------------------------------------------------
// CSR build: hist -> (merged two-phase scan, 25 co-resident blocks) -> fill
// ---------------------------------------------------------------------------
__global__ void hist_kernel(const int* __restrict__ dst) {
    int e = blockIdx.x * blockDim.x + threadIdx.x;
    if (e < E_EDGES) atomicAdd(&g_rowcnt[dst[e]], 1);
}

__global__ void scan_kernel() {
    __shared__ int sh[9];
    int tid = threadIdx.x;
    int bid = blockIdx.x;
    int lane = tid & 31, warp = tid >> 5;
    int base = bid * SCAN_BLK + tid * 8;

    // ---- phase A: block-local exclusive scan ----
    int v[8], s = 0;
#pragma unroll
    for (int j = 0; j < 8; j++) {
        int i = base + j;
        v[j] = (i < N_NODES) ? g_rowcnt[i] : 0;
        s += v[j];
    }
    int ps = s;
#pragma unroll
    for (int off = 1; off < 32; off <<= 1) {
        int n = __shfl_up_sync(0xffffffffu, ps, off);
        if (lane >= off) ps += n;
    }
    if (lane == 31) sh[warp] = ps;
    __syncthreads();
    if (warp == 0 && lane < 8) {
        int ws = sh[lane];
#pragma unroll
        for (int off = 1; off < 8; off <<= 1) {
            int n = __shfl_up_sync(0x000000ffu, ws, off);
            if (lane >= off) ws += n;
        }
        sh[lane] = ws;
    }
    __syncthreads();
    int woff = (warp == 0) ? 0 : sh[warp - 1];
    int excl = ps - s + woff;
    int run = excl;
    int local[8];
#pragma unroll
    for (int j = 0; j < 8; j++) {
        local[j] = run;
        run += v[j];
    }
    if (tid == 255) g_blocksum[bid] = run;

    // ---- grid barrier (25 blocks, all co-resident) ----
    __syncthreads();
    if (tid == 0) {
        int t = atomicAdd(&g_rowcnt[N_NODES], 1);
        if (t == SCAN_GRID - 1) {
            __threadfence();
            ((volatile int*)g_rowcnt)[N_NODES + 4] = 1;
        } else {
            while (((volatile int*)g_rowcnt)[N_NODES + 4] == 0) {}
            __threadfence();
        }
    }
    __syncthreads();

    // ---- phase B: block offsets + write rowptr/cursor ----
    if (tid < 32) {
        int l2 = tid;
        int bv = (l2 < SCAN_GRID) ? g_blocksum[l2] : 0;
        int bps = bv;
#pragma unroll
        for (int off = 1; off < 32; off <<= 1) {
            int n = __shfl_up_sync(0xffffffffu, bps, off);
            if (l2 >= off) bps += n;
        }
        if (l2 == bid) sh[8] = bps - bv;
        if (bid == SCAN_GRID - 1 && l2 == SCAN_GRID - 1)
            g_rowptr[N_NODES] = bps;
    }
    __syncthreads();
    int off = sh[8];
#pragma unroll
    for (int j = 0; j < 8; j++) {
        int i = base + j;
        if (i < N_NODES) {
            int p = local[j] + off;
            g_rowptr[i] = p;
            g_cursor[i] = p;
        }
    }
}

__global__ void fill_kernel(const int* __restrict__ src,
                            const int* __restrict__ dst) {
    int e = blockIdx.x * blockDim.x + threadIdx.x;
    if (e < E_EDGES) {
        int pos = atomicAdd(&g_cursor[dst[e]], 1);
        g_csr_src[pos] = src[e];
    }
}

// ---------------------------------------------------------------------------
// Gather layer 1 (fp32, 128 dims, warp per node) — 4x unrolled
// ---------------------------------------------------------------------------
__global__ void gather1_kernel(const float* __restrict__ x) {
    int node = (blockIdx.x * blockDim.x + threadIdx.x) >> 5;
    int lane = threadIdx.x & 31;
    if (node >= N_NODES) return;
    int beg = g_rowptr[node];
    int end = g_rowptr[node + 1];

    float4 acc = *reinterpret_cast<const float4*>(x + (size_t)node * D + lane * 4);

    for (int base = beg; base < end; base += 32) {
        int idx = 0;
        if (base + lane < end) idx = __ldg(&g_csr_src[base + lane]);
        int m = end - base; if (m > 32) m = 32;
        int j = 0;
        for (; j + 4 <= m; j += 4) {
            int s0 = __shfl_sync(0xffffffffu, idx, j);
            int s1 = __shfl_sync(0xffffffffu, idx, j + 1);
            int s2 = __shfl_sync(0xffffffffu, idx, j + 2);
            int s3 = __shfl_sync(0xffffffffu, idx, j + 3);
            float4 v0 = *reinterpret_cast<const float4*>(x + (size_t)s0 * D + lane * 4);
            float4 v1 = *reinterpret_cast<const float4*>(x + (size_t)s1 * D + lane * 4);
            float4 v2 = *reinterpret_cast<const float4*>(x + (size_t)s2 * D + lane * 4);
            float4 v3 = *reinterpret_cast<const float4*>(x + (size_t)s3 * D + lane * 4);
            acc.x += (v0.x + v1.x) + (v2.x + v3.x);
            acc.y += (v0.y + v1.y) + (v2.y + v3.y);
            acc.z += (v0.z + v1.z) + (v2.z + v3.z);
            acc.w += (v0.w + v1.w) + (v2.w + v3.w);
        }
        for (; j < m; j++) {
            int s = __shfl_sync(0xffffffffu, idx, j);
            float4 v = *reinterpret_cast<const float4*>(x + (size_t)s * D + lane * 4);
            acc.x += v.x; acc.y += v.y; acc.z += v.z; acc.w += v.w;
        }
    }
    float inv = 1.0f / (float)(end - beg + 1);
    acc.x *= inv; acc.y *= inv; acc.z *= inv; acc.w *= inv;
    *reinterpret_cast<float4*>(g_agg1 + (size_t)node * D + lane * 4) = acc;
}

// ---------------------------------------------------------------------------
// Fused GEMM via mma.sync tf32 (3xTF32 split), 512 threads / 128-row tile
// ---------------------------------------------------------------------------
#define ASTR 132
#define FG_SMEM ((D + 128 * ASTR + 2 * 128 * ASTR) * 4)

__global__ void __launch_bounds__(512, 1) fusedgemm_kernel() {
    extern __shared__ float sm[];
    float* bias = sm;
    float* sA   = sm + D;
    float* sWh  = sA + 128 * ASTR;
    float* sWl  = sWh + 128 * ASTR;

    int tid = threadIdx.x;
    int w = tid >> 5, lane = tid & 31;
    int g = lane >> 2, qi = lane & 3;
    int row0 = blockIdx.x * 128;

    if (tid < D) bias[tid] = g_bc[tid];
    for (int i = tid; i < 128 * 32; i += 512) {
        int r = i >> 5, c4 = (i & 31) << 2;
        float4 v = make_float4(0.f, 0.f, 0.f, 0.f);
        int row = row0 + r;
        if (row < N_NODES) v = *reinterpret_cast<const float4*>(g_agg1 + (size_t)row * D + c4);
        *reinterpret_cast<float4*>(&sA[r * ASTR + c4]) = v;
    }
    for (int i = tid; i < 128 * 32; i += 512) {
        int r = i >> 5, c4 = (i & 31) << 2;
        *reinterpret_cast<float4*>(&sWh[r * ASTR + c4]) =
            *reinterpret_cast<const float4*>(&g_WcT_h[r * D + c4]);
        *reinterpret_cast<float4*>(&sWl[r * ASTR + c4]) =
            *reinterpret_cast<const float4*>(&g_WcT_l[r * D + c4]);
    }
    __syncthreads();

    int rw0 = (w >> 2) * 32;
    int cw0 = (w & 3) * 32;
    float acc[2][4][4];
#pragma unroll
    for (int mt = 0; mt < 2; mt++)
#pragma unroll
        for (int nt = 0; nt < 4; nt++)
#pragma unroll
            for (int j = 0; j < 4; j++) acc[mt][nt][j] = 0.f;

#pragma unroll 4
    for (int ks = 0; ks < 16; ks++) {
        int k0 = ks * 8;
        uint32_t ah[2][4], al[2][4];
#pragma unroll
        for (int mt = 0; mt < 2; mt++) {
            int rb = rw0 + mt * 16;
            float f0 = sA[(rb + g) * ASTR + k0 + qi];
            float f1 = sA[(rb + g + 8) * ASTR + k0 + qi];
            float f2 = sA[(rb + g) * ASTR + k0 + qi + 4];
            float f3 = sA[(rb + g + 8) * ASTR + k0 + qi + 4];
            split_tf32(f0, ah[mt][0], al[mt][0]);
            split_tf32(f1, ah[mt][1], al[mt][1]);
            split_tf32(f2, ah[mt][2], al[mt][2]);
            split_tf32(f3, ah[mt][3], al[mt][3]);
        }
#pragma unroll
        for (int nt = 0; nt < 4; nt++) {
            int nb = cw0 + nt * 8;
            uint32_t bh0 = __float_as_uint(sWh[(nb + g) * ASTR + k0 + qi]);
            uint32_t bh1 = __float_as_uint(sWh[(nb + g) * ASTR + k0 + qi + 4]);
            uint32_t bl0 = __float_as_uint(sWl[(nb + g) * ASTR + k0 + qi]);
            uint32_t bl1 = __float_as_uint(sWl[(nb + g) * ASTR + k0 + qi + 4]);
#pragma unroll
            for (int mt = 0; mt < 2; mt++) {
                mma_tf32(acc[mt][nt], ah[mt], bh0, bh1);
                mma_tf32(acc[mt][nt], ah[mt], bl0, bl1);
                mma_tf32(acc[mt][nt], al[mt], bh0, bh1);
            }
        }
    }
    __syncthreads();

#pragma unroll
    for (int mt = 0; mt < 2; mt++) {
        int rb = rw0 + mt * 16;
#pragma unroll
        for (int nt = 0; nt < 4; nt++) {
            int c0 = cw0 + nt * 8 + qi * 2;
            float b0 = bias[c0], b1 = bias[c0 + 1];
            sA[(rb + g) * ASTR + c0]         = fmaxf(acc[mt][nt][0] + b0, 0.f);
            sA[(rb + g) * ASTR + c0 + 1]     = fmaxf(acc[mt][nt][1] + b1, 0.f);
            sA[(rb + g + 8) * ASTR + c0]     = fmaxf(acc[mt][nt][2] + b0, 0.f);
            sA[(rb + g + 8) * ASTR + c0 + 1] = fmaxf(acc[mt][nt][3] + b1, 0.f);
        }
    }
    __syncthreads();

    float* sW2h = sWh;
    float* sW2l = sWh + DOUT * ASTR;
    for (int i = tid; i < DOUT * 32; i += 512) {
        int r = i >> 5, c4 = (i & 31) << 2;
        *reinterpret_cast<float4*>(&sW2h[r * ASTR + c4]) =
            *reinterpret_cast<const float4*>(&g_W2T_h[r * D + c4]);
        *reinterpret_cast<float4*>(&sW2l[r * ASTR + c4]) =
            *reinterpret_cast<const float4*>(&g_W2T_l[r * D + c4]);
    }
    __syncthreads();

    int cw2 = (w & 3) * 16;
    float acc2[2][2][4];
#pragma unroll
    for (int mt = 0; mt < 2; mt++)
#pragma unroll
        for (int nt = 0; nt < 2; nt++)
#pragma unroll
            for (int j = 0; j < 4; j++) acc2[mt][nt][j] = 0.f;

#pragma unroll 4
    for (int ks = 0; ks < 16; ks++) {
        int k0 = ks * 8;
        uint32_t ah[2][4], al[2][4];
#pragma unroll
        for (int mt = 0; mt < 2; mt++) {
            int rb = rw0 + mt * 16;
            float f0 = sA[(rb + g) * ASTR + k0 + qi];
            float f1 = sA[(rb + g + 8) * ASTR + k0 + qi];
            float f2 = sA[(rb + g) * ASTR + k0 + qi + 4];
            float f3 = sA[(rb + g + 8) * ASTR + k0 + qi + 4];
            split_tf32(f0, ah[mt][0], al[mt][0]);
            split_tf32(f1, ah[mt][1], al[mt][1]);
            split_tf32(f2, ah[mt][2], al[mt][2]);
            split_tf32(f3, ah[mt][3], al[mt][3]);
        }
#pragma unroll
        for (int nt = 0; nt < 2; nt++) {
            int nb = cw2 + nt * 8;
            uint32_t bh0 = __float_as_uint(sW2h[(nb + g) * ASTR + k0 + qi]);
            uint32_t bh1 = __float_as_uint(sW2h[(nb + g) * ASTR + k0 + qi + 4]);
            uint32_t bl0 = __float_as_uint(sW2l[(nb + g) * ASTR + k0 + qi]);
            uint32_t bl1 = __float_as_uint(sW2l[(nb + g) * ASTR + k0 + qi + 4]);
#pragma unroll
            for (int mt = 0; mt < 2; mt++) {
                mma_tf32(acc2[mt][nt], ah[mt], bh0, bh1);
                mma_tf32(acc2[mt][nt], ah[mt], bl0, bl1);
                mma_tf32(acc2[mt][nt], al[mt], bh0, bh1);
            }
        }
    }
    __syncthreads();

    float* h2s = sA;
#pragma unroll
    for (int mt = 0; mt < 2; mt++) {
        int rb = rw0 + mt * 16;
#pragma unroll
        for (int nt = 0; nt < 2; nt++) {
            int c0 = cw2 + nt * 8 + qi * 2;
            h2s[(rb + g) * 66 + c0]         = acc2[mt][nt][0];
            h2s[(rb + g) * 66 + c0 + 1]     = acc2[mt][nt][1];
            h2s[(rb + g + 8) * 66 + c0]     = acc2[mt][nt][2];
            h2s[(rb + g + 8) * 66 + c0 + 1] = acc2[mt][nt][3];
        }
    }
    __syncthreads();
    for (int i = tid; i < 128 * 32; i += 512) {
        int r = i >> 5, c2 = (i & 31) << 1;
        int row = row0 + r;
        if (row < N_NODES) {
            float2 v = *reinterpret_cast<const float2*>(&h2s[r * 66 + c2]);
            *reinterpret_cast<float2*>(&g_h2[(size_t)row * DOUT + c2]) = v;
        }
    }
}

// ---------------------------------------------------------------------------
// Gather layer 2 + bias + L2 normalize: HALF-WARP per node, float4 lanes
// ---------------------------------------------------------------------------
__global__ void gather2_kernel(const float* __restrict__ b2,
                               float* __restrict__ out) {
    int gw = (blockIdx.x * blockDim.x + threadIdx.x) >> 5;
    int lane = threadIdx.x & 31;
    int half = lane >> 4, l = lane & 15;
    int node = gw * 2 + half;
    if (node >= N_NODES) return;
    unsigned hmask = 0xFFFFu << (half * 16);
    int sbase = half * 16;

    int beg = g_rowptr[node];
    int end = g_rowptr[node + 1];

    float4 acc = *reinterpret_cast<const float4*>(g_h2 + (size_t)node * DOUT + l * 4);

    for (int base = beg; base < end; base += 16) {
        int idx = 0;
        if (base + l < end) idx = __ldg(&g_csr_src[base + l]);
        int m = end - base; if (m > 16) m = 16;
        int j = 0;
        for (; j + 4 <= m; j += 4) {
            int s0 = __shfl_sync(hmask, idx, sbase + j);
            int s1 = __shfl_sync(hmask, idx, sbase + j + 1);
            int s2 = __shfl_sync(hmask, idx, sbase + j + 2);
            int s3 = __shfl_sync(hmask, idx, sbase + j + 3);
            float4 v0 = *reinterpret_cast<const float4*>(g_h2 + (size_t)s0 * DOUT + l * 4);
            float4 v1 = *reinterpret_cast<const float4*>(g_h2 + (size_t)s1 * DOUT + l * 4);
            float4 v2 = *reinterpret_cast<const float4*>(g_h2 + (size_t)s2 * DOUT + l * 4);
            float4 v3 = *reinterpret_cast<const float4*>(g_h2 + (size_t)s3 * DOUT + l * 4);
            acc.x += (v0.x + v1.x) + (v2.x + v3.x);
            acc.y += (v0.y + v1.y) + (v2.y + v3.y);
            acc.z += (v0.z + v1.z) + (v2.z + v3.z);
            acc.w += (v0.w + v1.w) + (v2.w + v3.w);
        }
        for (; j < m; j++) {
            int s = __shfl_sync(hmask, idx, sbase + j);
            float4 v = *reinterpret_cast<const float4*>(g_h2 + (size_t)s * DOUT + l * 4);
            acc.x += v.x; acc.y += v.y; acc.z += v.z; acc.w += v.w;
        }
    }
    float inv = 1.0f / (float)(end - beg + 1);
    float4 b = *reinterpret_cast<const float4*>(b2 + l * 4);
    float a0 = acc.x * inv + b.x;
    float a1 = acc.y * inv + b.y;
    float a2 = acc.z * inv + b.z;
    float a3 = acc.w * inv + b.w;
    float ss = a0 * a0 + a1 * a1 + a2 * a2 + a3 * a3;
#pragma unroll
    for (int o = 8; o; o >>= 1) ss += __shfl_xor_sync(hmask, ss, o);
    float s = 1.0f / fmaxf(sqrtf(ss), 1e-12f);
    float4 o4 = make_float4(a0 * s, a1 * s, a2 * s, a3 * s);
    *reinterpret_cast<float4*>(&out[(size_t)node * DOUT + l * 4]) = o4;
}

// ---------------------------------------------------------------------------
extern "C" void kernel_launch(void* const* d_in, const int* in_sizes, int n_in,
                              void* d_out, int out_size) {
    const float* x     = (const float*)d_in[0];
    const int*   ei    = (const int*)d_in[1];
    const float* W_pre = (const float*)d_in[2];
    const float* b_pre = (const float*)d_in[3];
    const float* W1    = (const float*)d_in[4];
    const float* b1    = (const float*)d_in[5];
    const float* W2    = (const float*)d_in[6];
    const float* b2    = (const float*)d_in[7];
    float* out = (float*)d_out;

    const int* src = ei;
    const int* dst = ei + E_EDGES;

    static void* rowcnt_ptr = nullptr;
    static bool attr_set = false;
    if (!attr_set) {
        cudaFuncSetAttribute(fusedgemm_kernel,
                             cudaFuncAttributeMaxDynamicSharedMemorySize, FG_SMEM);
        cudaGetSymbolAddress(&rowcnt_ptr, g_rowcnt);
        attr_set = true;
    }

    prep_kernel<<<D + 1 + DOUT, D>>>(W_pre, b_pre, W1, b1, W2);
    cudaMemsetAsync(rowcnt_ptr, 0, (N_NODES + 8) * sizeof(int));
    hist_kernel<<<(E_EDGES + 255) / 256, 256>>>(dst);
    scan_kernel<<<SCAN_GRID, 256>>>();
    fill_kernel<<<(E_EDGES + 255) / 256, 256>>>(src, dst);
    gather1_kernel<<<(N_NODES * 32 + 255) / 256, 256>>>(x);
    fusedgemm_kernel<<<(N_NODES + 127) / 128, 512, FG_SMEM>>>();
    gather2_kernel<<<((N_NODES + 1) / 2 * 32 + 255) / 256, 256>>>(b2, out);
}

// round 10
// speedup vs baseline: 1.4958x; 1.0242x over previous
#include <cuda_runtime.h>
#include <cstdint>

#define N_NODES 50000
#define D 128
#define DOUT 64
#define E_EDGES 800000

#define SCAN_BLK 2048
#define SCAN_GRID 25   // 25 blocks, co-resident by construction

// ---------------- device globals (no allocation allowed) ----------------
__device__ __align__(16) float g_agg1[N_NODES * D];
__device__ __align__(16) float g_h2[N_NODES * DOUT];
__device__ __align__(16) float g_bc[D];
// [0..N) = histogram; [N..N+8) = barrier counter/flag scratch
__device__ int g_rowcnt[N_NODES + 8];
__device__ int g_rowptr[N_NODES + 1];
__device__ __align__(16) int g_rank[E_EDGES];
__device__ int g_csr_src[E_EDGES];
__device__ int g_blocksum[SCAN_GRID];
// tf32 split weight images, transposed: [out_col][k]
__device__ __align__(16) float g_WcT_h[D * D];
__device__ __align__(16) float g_WcT_l[D * D];
__device__ __align__(16) float g_W2T_h[DOUT * D];
__device__ __align__(16) float g_W2T_l[DOUT * D];

// ---------------- tf32 helpers ----------------
__device__ __forceinline__ uint32_t f2tf32(float f) {
    uint32_t r;
    asm("cvt.rna.tf32.f32 %0, %1;" : "=r"(r) : "f"(f));
    return r;
}

__device__ __forceinline__ void split_tf32(float a, uint32_t& hi, uint32_t& lo) {
    hi = f2tf32(a);
    lo = f2tf32(a - __uint_as_float(hi));
}

__device__ __forceinline__ void mma_tf32(float* d, const uint32_t* a,
                                         uint32_t b0, uint32_t b1) {
    asm volatile(
        "mma.sync.aligned.m16n8k8.row.col.f32.tf32.tf32.f32 "
        "{%0,%1,%2,%3}, {%4,%5,%6,%7}, {%8,%9}, {%0,%1,%2,%3};"
        : "+f"(d[0]), "+f"(d[1]), "+f"(d[2]), "+f"(d[3])
        : "r"(a[0]), "r"(a[1]), "r"(a[2]), "r"(a[3]), "r"(b0), "r"(b1));
}

// ---------------------------------------------------------------------------
// Merged prep + rowcnt zeroing
// ---------------------------------------------------------------------------
__global__ void prep_kernel(const float* __restrict__ W_pre,
                            const float* __restrict__ b_pre,
                            const float* __restrict__ W1,
                            const float* __restrict__ b1,
                            const float* __restrict__ W2) {
    int c = threadIdx.x;
    int r = blockIdx.x;
    // zero histogram + barrier scratch (grid-stride over all prep threads)
    int gid = r * D + c;
    int nthreads = gridDim.x * D;
    for (int i = gid; i < N_NODES + 8; i += nthreads) g_rowcnt[i] = 0;

    if (r < D) {
        float acc = 0.f;
#pragma unroll 8
        for (int k = 0; k < D; k++) acc += W_pre[r * D + k] * W1[k * D + c];
        uint32_t hi, lo;
        split_tf32(acc, hi, lo);
        g_WcT_h[c * D + r] = __uint_as_float(hi);
        g_WcT_l[c * D + r] = __uint_as_float(lo);
    } else if (r == D) {
        float acc = b1[c];
#pragma unroll 8
        for (int k = 0; k < D; k++) acc += b_pre[k] * W1[k * D + c];
        g_bc[c] = acc;
    } else {
        int n = r - D - 1;
        uint32_t hi, lo;
        split_tf32(W2[c * DOUT + n], hi, lo);
        g_W2T_h[n * D + c] = __uint_as_float(hi);
        g_W2T_l[n * D + c] = __uint_as_float(lo);
    }
}

// ---------------------------------------------------------------------------
// CSR build: hist(+rank) -> merged two-phase scan -> fill (no atomics)
// ---------------------------------------------------------------------------
__global__ void hist_kernel(const int* __restrict__ dst) {
    int e = blockIdx.x * blockDim.x + threadIdx.x;
    if (e < E_EDGES) {
        int d = __ldg(&dst[e]);
        int old = atomicAdd(&g_rowcnt[d], 1);
        g_rank[e] = old;
    }
}

__global__ void scan_kernel() {
    __shared__ int sh[9];
    int tid = threadIdx.x;
    int bid = blockIdx.x;
    int lane = tid & 31, warp = tid >> 5;
    int base = bid * SCAN_BLK + tid * 8;

    // ---- phase A: block-local exclusive scan ----
    int v[8], s = 0;
#pragma unroll
    for (int j = 0; j < 8; j++) {
        int i = base + j;
        v[j] = (i < N_NODES) ? g_rowcnt[i] : 0;
        s += v[j];
    }
    int ps = s;
#pragma unroll
    for (int off = 1; off < 32; off <<= 1) {
        int n = __shfl_up_sync(0xffffffffu, ps, off);
        if (lane >= off) ps += n;
    }
    if (lane == 31) sh[warp] = ps;
    __syncthreads();
    if (warp == 0 && lane < 8) {
        int ws = sh[lane];
#pragma unroll
        for (int off = 1; off < 8; off <<= 1) {
            int n = __shfl_up_sync(0x000000ffu, ws, off);
            if (lane >= off) ws += n;
        }
        sh[lane] = ws;
    }
    __syncthreads();
    int woff = (warp == 0) ? 0 : sh[warp - 1];
    int excl = ps - s + woff;
    int run = excl;
    int local[8];
#pragma unroll
    for (int j = 0; j < 8; j++) {
        local[j] = run;
        run += v[j];
    }
    if (tid == 255) g_blocksum[bid] = run;

    // ---- grid barrier (25 blocks, all co-resident) ----
    __syncthreads();
    if (tid == 0) {
        int t = atomicAdd(&g_rowcnt[N_NODES], 1);
        if (t == SCAN_GRID - 1) {
            __threadfence();
            ((volatile int*)g_rowcnt)[N_NODES + 4] = 1;
        } else {
            while (((volatile int*)g_rowcnt)[N_NODES + 4] == 0) {}
            __threadfence();
        }
    }
    __syncthreads();

    // ---- phase B: block offsets + write rowptr ----
    if (tid < 32) {
        int l2 = tid;
        int bv = (l2 < SCAN_GRID) ? g_blocksum[l2] : 0;
        int bps = bv;
#pragma unroll
        for (int off = 1; off < 32; off <<= 1) {
            int n = __shfl_up_sync(0xffffffffu, bps, off);
            if (l2 >= off) bps += n;
        }
        if (l2 == bid) sh[8] = bps - bv;
        if (bid == SCAN_GRID - 1 && l2 == SCAN_GRID - 1)
            g_rowptr[N_NODES] = bps;
    }
    __syncthreads();
    int off = sh[8];
#pragma unroll
    for (int j = 0; j < 8; j++) {
        int i = base + j;
        if (i < N_NODES) g_rowptr[i] = local[j] + off;
    }
}

// fill: no atomics — pos = rowptr[dst] + rank; 4 edges per thread
__global__ void fill_kernel(const int* __restrict__ src,
                            const int* __restrict__ dst) {
    int e4 = (blockIdx.x * blockDim.x + threadIdx.x) * 4;
    if (e4 < E_EDGES) {   // E_EDGES % 4 == 0
        int4 s = *reinterpret_cast<const int4*>(src + e4);
        int4 d = *reinterpret_cast<const int4*>(dst + e4);
        int4 r = *reinterpret_cast<const int4*>(g_rank + e4);
        g_csr_src[g_rowptr[d.x] + r.x] = s.x;
        g_csr_src[g_rowptr[d.y] + r.y] = s.y;
        g_csr_src[g_rowptr[d.z] + r.z] = s.z;
        g_csr_src[g_rowptr[d.w] + r.w] = s.w;
    }
}

// ---------------------------------------------------------------------------
// Gather layer 1 (fp32, 128 dims, warp per node) — 4x unrolled
// ---------------------------------------------------------------------------
__global__ void gather1_kernel(const float* __restrict__ x) {
    int node = (blockIdx.x * blockDim.x + threadIdx.x) >> 5;
    int lane = threadIdx.x & 31;
    if (node >= N_NODES) return;
    int beg = g_rowptr[node];
    int end = g_rowptr[node + 1];

    float4 acc = *reinterpret_cast<const float4*>(x + (size_t)node * D + lane * 4);

    for (int base = beg; base < end; base += 32) {
        int idx = 0;
        if (base + lane < end) idx = __ldg(&g_csr_src[base + lane]);
        int m = end - base; if (m > 32) m = 32;
        int j = 0;
        for (; j + 4 <= m; j += 4) {
            int s0 = __shfl_sync(0xffffffffu, idx, j);
            int s1 = __shfl_sync(0xffffffffu, idx, j + 1);
            int s2 = __shfl_sync(0xffffffffu, idx, j + 2);
            int s3 = __shfl_sync(0xffffffffu, idx, j + 3);
            float4 v0 = *reinterpret_cast<const float4*>(x + (size_t)s0 * D + lane * 4);
            float4 v1 = *reinterpret_cast<const float4*>(x + (size_t)s1 * D + lane * 4);
            float4 v2 = *reinterpret_cast<const float4*>(x + (size_t)s2 * D + lane * 4);
            float4 v3 = *reinterpret_cast<const float4*>(x + (size_t)s3 * D + lane * 4);
            acc.x += (v0.x + v1.x) + (v2.x + v3.x);
            acc.y += (v0.y + v1.y) + (v2.y + v3.y);
            acc.z += (v0.z + v1.z) + (v2.z + v3.z);
            acc.w += (v0.w + v1.w) + (v2.w + v3.w);
        }
        for (; j < m; j++) {
            int s = __shfl_sync(0xffffffffu, idx, j);
            float4 v = *reinterpret_cast<const float4*>(x + (size_t)s * D + lane * 4);
            acc.x += v.x; acc.y += v.y; acc.z += v.z; acc.w += v.w;
        }
    }
    float inv = 1.0f / (float)(end - beg + 1);
    acc.x *= inv; acc.y *= inv; acc.z *= inv; acc.w *= inv;
    *reinterpret_cast<float4*>(g_agg1 + (size_t)node * D + lane * 4) = acc;
}

// ---------------------------------------------------------------------------
// Fused GEMM via mma.sync tf32 (3xTF32 split), 512 threads / 128-row tile
// ---------------------------------------------------------------------------
#define ASTR 132
#define FG_SMEM ((D + 128 * ASTR + 2 * 128 * ASTR) * 4)

__global__ void __launch_bounds__(512, 1) fusedgemm_kernel() {
    extern __shared__ float sm[];
    float* bias = sm;
    float* sA   = sm + D;
    float* sWh  = sA + 128 * ASTR;
    float* sWl  = sWh + 128 * ASTR;

    int tid = threadIdx.x;
    int w = tid >> 5, lane = tid & 31;
    int g = lane >> 2, qi = lane & 3;
    int row0 = blockIdx.x * 128;

    if (tid < D) bias[tid] = g_bc[tid];
    for (int i = tid; i < 128 * 32; i += 512) {
        int r = i >> 5, c4 = (i & 31) << 2;
        float4 v = make_float4(0.f, 0.f, 0.f, 0.f);
        int row = row0 + r;
        if (row < N_NODES) v = *reinterpret_cast<const float4*>(g_agg1 + (size_t)row * D + c4);
        *reinterpret_cast<float4*>(&sA[r * ASTR + c4]) = v;
    }
    for (int i = tid; i < 128 * 32; i += 512) {
        int r = i >> 5, c4 = (i & 31) << 2;
        *reinterpret_cast<float4*>(&sWh[r * ASTR + c4]) =
            *reinterpret_cast<const float4*>(&g_WcT_h[r * D + c4]);
        *reinterpret_cast<float4*>(&sWl[r * ASTR + c4]) =
            *reinterpret_cast<const float4*>(&g_WcT_l[r * D + c4]);
    }
    __syncthreads();

    int rw0 = (w >> 2) * 32;
    int cw0 = (w & 3) * 32;
    float acc[2][4][4];
#pragma unroll
    for (int mt = 0; mt < 2; mt++)
#pragma unroll
        for (int nt = 0; nt < 4; nt++)
#pragma unroll
            for (int j = 0; j < 4; j++) acc[mt][nt][j] = 0.f;

#pragma unroll 4
    for (int ks = 0; ks < 16; ks++) {
        int k0 = ks * 8;
        uint32_t ah[2][4], al[2][4];
#pragma unroll
        for (int mt = 0; mt < 2; mt++) {
            int rb = rw0 + mt * 16;
            float f0 = sA[(rb + g) * ASTR + k0 + qi];
            float f1 = sA[(rb + g + 8) * ASTR + k0 + qi];
            float f2 = sA[(rb + g) * ASTR + k0 + qi + 4];
            float f3 = sA[(rb + g + 8) * ASTR + k0 + qi + 4];
            split_tf32(f0, ah[mt][0], al[mt][0]);
            split_tf32(f1, ah[mt][1], al[mt][1]);
            split_tf32(f2, ah[mt][2], al[mt][2]);
            split_tf32(f3, ah[mt][3], al[mt][3]);
        }
#pragma unroll
        for (int nt = 0; nt < 4; nt++) {
            int nb = cw0 + nt * 8;
            uint32_t bh0 = __float_as_uint(sWh[(nb + g) * ASTR + k0 + qi]);
            uint32_t bh1 = __float_as_uint(sWh[(nb + g) * ASTR + k0 + qi + 4]);
            uint32_t bl0 = __float_as_uint(sWl[(nb + g) * ASTR + k0 + qi]);
            uint32_t bl1 = __float_as_uint(sWl[(nb + g) * ASTR + k0 + qi + 4]);
#pragma unroll
            for (int mt = 0; mt < 2; mt++) {
                mma_tf32(acc[mt][nt], ah[mt], bh0, bh1);
                mma_tf32(acc[mt][nt], ah[mt], bl0, bl1);
                mma_tf32(acc[mt][nt], al[mt], bh0, bh1);
            }
        }
    }
    __syncthreads();

#pragma unroll
    for (int mt = 0; mt < 2; mt++) {
        int rb = rw0 + mt * 16;
#pragma unroll
        for (int nt = 0; nt < 4; nt++) {
            int c0 = cw0 + nt * 8 + qi * 2;
            float b0 = bias[c0], b1 = bias[c0 + 1];
            sA[(rb + g) * ASTR + c0]         = fmaxf(acc[mt][nt][0] + b0, 0.f);
            sA[(rb + g) * ASTR + c0 + 1]     = fmaxf(acc[mt][nt][1] + b1, 0.f);
            sA[(rb + g + 8) * ASTR + c0]     = fmaxf(acc[mt][nt][2] + b0, 0.f);
            sA[(rb + g + 8) * ASTR + c0 + 1] = fmaxf(acc[mt][nt][3] + b1, 0.f);
        }
    }
    __syncthreads();

    float* sW2h = sWh;
    float* sW2l = sWh + DOUT * ASTR;
    for (int i = tid; i < DOUT * 32; i += 512) {
        int r = i >> 5, c4 = (i & 31) << 2;
        *reinterpret_cast<float4*>(&sW2h[r * ASTR + c4]) =
            *reinterpret_cast<const float4*>(&g_W2T_h[r * D + c4]);
        *reinterpret_cast<float4*>(&sW2l[r * ASTR + c4]) =
            *reinterpret_cast<const float4*>(&g_W2T_l[r * D + c4]);
    }
    __syncthreads();

    int cw2 = (w & 3) * 16;
    float acc2[2][2][4];
#pragma unroll
    for (int mt = 0; mt < 2; mt++)
#pragma unroll
        for (int nt = 0; nt < 2; nt++)
#pragma unroll
            for (int j = 0; j < 4; j++) acc2[mt][nt][j] = 0.f;

#pragma unroll 4
    for (int ks = 0; ks < 16; ks++) {
        int k0 = ks * 8;
        uint32_t ah[2][4], al[2][4];
#pragma unroll
        for (int mt = 0; mt < 2; mt++) {
            int rb = rw0 + mt * 16;
            float f0 = sA[(rb + g) * ASTR + k0 + qi];
            float f1 = sA[(rb + g + 8) * ASTR + k0 + qi];
            float f2 = sA[(rb + g) * ASTR + k0 + qi + 4];
            float f3 = sA[(rb + g + 8) * ASTR + k0 + qi + 4];
            split_tf32(f0, ah[mt][0], al[mt][0]);
            split_tf32(f1, ah[mt][1], al[mt][1]);
            split_tf32(f2, ah[mt][2], al[mt][2]);
            split_tf32(f3, ah[mt][3], al[mt][3]);
        }
#pragma unroll
        for (int nt = 0; nt < 2; nt++) {
            int nb = cw2 + nt * 8;
            uint32_t bh0 = __float_as_uint(sW2h[(nb + g) * ASTR + k0 + qi]);
            uint32_t bh1 = __float_as_uint(sW2h[(nb + g) * ASTR + k0 + qi + 4]);
            uint32_t bl0 = __float_as_uint(sW2l[(nb + g) * ASTR + k0 + qi]);
            uint32_t bl1 = __float_as_uint(sW2l[(nb + g) * ASTR + k0 + qi + 4]);
#pragma unroll
            for (int mt = 0; mt < 2; mt++) {
                mma_tf32(acc2[mt][nt], ah[mt], bh0, bh1);
                mma_tf32(acc2[mt][nt], ah[mt], bl0, bl1);
                mma_tf32(acc2[mt][nt], al[mt], bh0, bh1);
            }
        }
    }
    __syncthreads();

    float* h2s = sA;
#pragma unroll
    for (int mt = 0; mt < 2; mt++) {
        int rb = rw0 + mt * 16;
#pragma unroll
        for (int nt = 0; nt < 2; nt++) {
            int c0 = cw2 + nt * 8 + qi * 2;
            h2s[(rb + g) * 66 + c0]         = acc2[mt][nt][0];
            h2s[(rb + g) * 66 + c0 + 1]     = acc2[mt][nt][1];
            h2s[(rb + g + 8) * 66 + c0]     = acc2[mt][nt][2];
            h2s[(rb + g + 8) * 66 + c0 + 1] = acc2[mt][nt][3];
        }
    }
    __syncthreads();
    for (int i = tid; i < 128 * 32; i += 512) {
        int r = i >> 5, c2 = (i & 31) << 1;
        int row = row0 + r;
        if (row < N_NODES) {
            float2 v = *reinterpret_cast<const float2*>(&h2s[r * 66 + c2]);
            *reinterpret_cast<float2*>(&g_h2[(size_t)row * DOUT + c2]) = v;
        }
    }
}

// ---------------------------------------------------------------------------
// Gather layer 2 + bias + L2 normalize: HALF-WARP per node, float4 lanes
// ---------------------------------------------------------------------------
__global__ void gather2_kernel(const float* __restrict__ b2,
                               float* __restrict__ out) {
    int gw = (blockIdx.x * blockDim.x + threadIdx.x) >> 5;
    int lane = threadIdx.x & 31;
    int half = lane >> 4, l = lane & 15;
    int node = gw * 2 + half;
    if (node >= N_NODES) return;
    unsigned hmask = 0xFFFFu << (half * 16);
    int sbase = half * 16;

    int beg = g_rowptr[node];
    int end = g_rowptr[node + 1];

    float4 acc = *reinterpret_cast<const float4*>(g_h2 + (size_t)node * DOUT + l * 4);

    for (int base = beg; base < end; base += 16) {
        int idx = 0;
        if (base + l < end) idx = __ldg(&g_csr_src[base + l]);
        int m = end - base; if (m > 16) m = 16;
        int j = 0;
        for (; j + 4 <= m; j += 4) {
            int s0 = __shfl_sync(hmask, idx, sbase + j);
            int s1 = __shfl_sync(hmask, idx, sbase + j + 1);
            int s2 = __shfl_sync(hmask, idx, sbase + j + 2);
            int s3 = __shfl_sync(hmask, idx, sbase + j + 3);
            float4 v0 = *reinterpret_cast<const float4*>(g_h2 + (size_t)s0 * DOUT + l * 4);
            float4 v1 = *reinterpret_cast<const float4*>(g_h2 + (size_t)s1 * DOUT + l * 4);
            float4 v2 = *reinterpret_cast<const float4*>(g_h2 + (size_t)s2 * DOUT + l * 4);
            float4 v3 = *reinterpret_cast<const float4*>(g_h2 + (size_t)s3 * DOUT + l * 4);
            acc.x += (v0.x + v1.x) + (v2.x + v3.x);
            acc.y += (v0.y + v1.y) + (v2.y + v3.y);
            acc.z += (v0.z + v1.z) + (v2.z + v3.z);
            acc.w += (v0.w + v1.w) + (v2.w + v3.w);
        }
        for (; j < m; j++) {
            int s = __shfl_sync(hmask, idx, sbase + j);
            float4 v = *reinterpret_cast<const float4*>(g_h2 + (size_t)s * DOUT + l * 4);
            acc.x += v.x; acc.y += v.y; acc.z += v.z; acc.w += v.w;
        }
    }
    float inv = 1.0f / (float)(end - beg + 1);
    float4 b = *reinterpret_cast<const float4*>(b2 + l * 4);
    float a0 = acc.x * inv + b.x;
    float a1 = acc.y * inv + b.y;
    float a2 = acc.z * inv + b.z;
    float a3 = acc.w * inv + b.w;
    float ss = a0 * a0 + a1 * a1 + a2 * a2 + a3 * a3;
#pragma unroll
    for (int o = 8; o; o >>= 1) ss += __shfl_xor_sync(hmask, ss, o);
    float s = 1.0f / fmaxf(sqrtf(ss), 1e-12f);
    float4 o4 = make_float4(a0 * s, a1 * s, a2 * s, a3 * s);
    *reinterpret_cast<float4*>(&out[(size_t)node * DOUT + l * 4]) = o4;
}

// ---------------------------------------------------------------------------
extern "C" void kernel_launch(void* const* d_in, const int* in_sizes, int n_in,
                              void* d_out, int out_size) {
    const float* x     = (const float*)d_in[0];
    const int*   ei    = (const int*)d_in[1];
    const float* W_pre = (const float*)d_in[2];
    const float* b_pre = (const float*)d_in[3];
    const float* W1    = (const float*)d_in[4];
    const float* b1    = (const float*)d_in[5];
    const float* W2    = (const float*)d_in[6];
    const float* b2    = (const float*)d_in[7];
    float* out = (float*)d_out;

    const int* src = ei;
    const int* dst = ei + E_EDGES;

    static bool attr_set = false;
    if (!attr_set) {
        cudaFuncSetAttribute(fusedgemm_kernel,
                             cudaFuncAttributeMaxDynamicSharedMemorySize, FG_SMEM);
        attr_set = true;
    }

    prep_kernel<<<D + 1 + DOUT, D>>>(W_pre, b_pre, W1, b1, W2);
    hist_kernel<<<(E_EDGES + 255) / 256, 256>>>(dst);
    scan_kernel<<<SCAN_GRID, 256>>>();
    fill_kernel<<<(E_EDGES / 4 + 255) / 256, 256>>>(src, dst);
    gather1_kernel<<<(N_NODES * 32 + 255) / 256, 256>>>(x);
    fusedgemm_kernel<<<(N_NODES + 127) / 128, 512, FG_SMEM>>>();
    gather2_kernel<<<((N_NODES + 1) / 2 * 32 + 255) / 256, 256>>>(b2, out);
}

// round 11
// speedup vs baseline: 1.5574x; 1.0412x over previous
#include <cuda_runtime.h>
#include <cstdint>

#define N_NODES 50000
#define D 128
#define DOUT 64
#define E_EDGES 800000

#define SCAN_BLK 2048
#define SCAN_GRID 25   // 25 blocks, co-resident by construction

#define PREP_THREADS ((D + 1 + DOUT) * D)          // 24704
#define PREP_BLOCKS ((PREP_THREADS + 255) / 256)   // 97
#define HIST_BLOCKS ((E_EDGES / 4 + 255) / 256)    // 782
#define PH_BLOCKS (PREP_BLOCKS + HIST_BLOCKS)

// ---------------- device globals (zero-initialized at module load) --------
__device__ __align__(16) float g_agg1[N_NODES * D];
__device__ __align__(16) float g_h2[N_NODES * DOUT];
__device__ __align__(16) float g_bc[D];
// [0..N) = histogram (re-zeroed by scan each run); [N]=arrive ctr, [N+1]=done ctr, [N+4]=flag
__device__ int g_rowcnt[N_NODES + 8];
__device__ int g_rowptr[N_NODES + 1];
__device__ __align__(16) int g_rank[E_EDGES];
__device__ int g_csr_src[E_EDGES];
__device__ int g_blocksum[SCAN_GRID];
// tf32 split weight images, transposed: [out_col][k]
__device__ __align__(16) float g_WcT_h[D * D];
__device__ __align__(16) float g_WcT_l[D * D];
__device__ __align__(16) float g_W2T_h[DOUT * D];
__device__ __align__(16) float g_W2T_l[DOUT * D];

// ---------------- tf32 helpers ----------------
__device__ __forceinline__ uint32_t f2tf32(float f) {
    uint32_t r;
    asm("cvt.rna.tf32.f32 %0, %1;" : "=r"(r) : "f"(f));
    return r;
}

__device__ __forceinline__ void split_tf32(float a, uint32_t& hi, uint32_t& lo) {
    hi = f2tf32(a);
    lo = f2tf32(a - __uint_as_float(hi));
}

__device__ __forceinline__ void mma_tf32(float* d, const uint32_t* a,
                                         uint32_t b0, uint32_t b1) {
    asm volatile(
        "mma.sync.aligned.m16n8k8.row.col.f32.tf32.tf32.f32 "
        "{%0,%1,%2,%3}, {%4,%5,%6,%7}, {%8,%9}, {%0,%1,%2,%3};"
        : "+f"(d[0]), "+f"(d[1]), "+f"(d[2]), "+f"(d[3])
        : "r"(a[0]), "r"(a[1]), "r"(a[2]), "r"(a[3]), "r"(b0), "r"(b1));
}

// ---------------------------------------------------------------------------
// Merged prep + hist: blocks [0,97) do weight prep; blocks [97,879) histogram
// (g_rowcnt is zero at entry: zero-init on first run, re-zeroed by scan after)
// ---------------------------------------------------------------------------
__global__ void prephist_kernel(const int* __restrict__ dst,
                                const float* __restrict__ W_pre,
                                const float* __restrict__ b_pre,
                                const float* __restrict__ W1,
                                const float* __restrict__ b1,
                                const float* __restrict__ W2) {
    int bid = blockIdx.x;
    int tid = threadIdx.x;
    if (bid < PREP_BLOCKS) {
        int gid = bid * 256 + tid;
        if (gid >= PREP_THREADS) return;
        int r = gid >> 7;
        int c = gid & 127;
        if (r < D) {
            float acc = 0.f;
#pragma unroll 8
            for (int k = 0; k < D; k++) acc += W_pre[r * D + k] * W1[k * D + c];
            uint32_t hi, lo;
            split_tf32(acc, hi, lo);
            g_WcT_h[c * D + r] = __uint_as_float(hi);
            g_WcT_l[c * D + r] = __uint_as_float(lo);
        } else if (r == D) {
            float acc = b1[c];
#pragma unroll 8
            for (int k = 0; k < D; k++) acc += b_pre[k] * W1[k * D + c];
            g_bc[c] = acc;
        } else {
            int n = r - D - 1;
            uint32_t hi, lo;
            split_tf32(W2[c * DOUT + n], hi, lo);
            g_W2T_h[n * D + c] = __uint_as_float(hi);
            g_W2T_l[n * D + c] = __uint_as_float(lo);
        }
    } else {
        int e4 = ((bid - PREP_BLOCKS) * 256 + tid) * 4;
        if (e4 < E_EDGES) {   // E_EDGES % 4 == 0
            int4 d = *reinterpret_cast<const int4*>(dst + e4);
            int4 rk;
            rk.x = atomicAdd(&g_rowcnt[d.x], 1);
            rk.y = atomicAdd(&g_rowcnt[d.y], 1);
            rk.z = atomicAdd(&g_rowcnt[d.z], 1);
            rk.w = atomicAdd(&g_rowcnt[d.w], 1);
            *reinterpret_cast<int4*>(g_rank + e4) = rk;
        }
    }
}

// ---------------------------------------------------------------------------
// Scan (25 co-resident blocks): exclusive scan of rowcnt -> rowptr.
// Re-zeroes rowcnt after reading; resets barrier scratch for next replay.
// ---------------------------------------------------------------------------
__global__ void scan_kernel() {
    __shared__ int sh[9];
    int tid = threadIdx.x;
    int bid = blockIdx.x;
    int lane = tid & 31, warp = tid >> 5;
    int base = bid * SCAN_BLK + tid * 8;

    // ---- phase A: read counts, zero them for the next replay ----
    int v[8], s = 0;
#pragma unroll
    for (int j = 0; j < 8; j++) {
        int i = base + j;
        v[j] = (i < N_NODES) ? g_rowcnt[i] : 0;
        if (i < N_NODES) g_rowcnt[i] = 0;
        s += v[j];
    }
    int ps = s;
#pragma unroll
    for (int off = 1; off < 32; off <<= 1) {
        int n = __shfl_up_sync(0xffffffffu, ps, off);
        if (lane >= off) ps += n;
    }
    if (lane == 31) sh[warp] = ps;
    __syncthreads();
    if (warp == 0 && lane < 8) {
        int ws = sh[lane];
#pragma unroll
        for (int off = 1; off < 8; off <<= 1) {
            int n = __shfl_up_sync(0x000000ffu, ws, off);
            if (lane >= off) ws += n;
        }
        sh[lane] = ws;
    }
    __syncthreads();
    int woff = (warp == 0) ? 0 : sh[warp - 1];
    int excl = ps - s + woff;
    int run = excl;
    int local[8];
#pragma unroll
    for (int j = 0; j < 8; j++) {
        local[j] = run;
        run += v[j];
    }
    if (tid == 255) g_blocksum[bid] = run;

    // ---- grid barrier ----
    __syncthreads();
    if (tid == 0) {
        int t = atomicAdd(&g_rowcnt[N_NODES], 1);
        if (t == SCAN_GRID - 1) {
            __threadfence();
            ((volatile int*)g_rowcnt)[N_NODES + 4] = 1;
        } else {
            while (((volatile int*)g_rowcnt)[N_NODES + 4] == 0) {}
            __threadfence();
        }
    }
    __syncthreads();

    // ---- phase B: block offsets + write rowptr ----
    if (tid < 32) {
        int l2 = tid;
        int bv = (l2 < SCAN_GRID) ? g_blocksum[l2] : 0;
        int bps = bv;
#pragma unroll
        for (int off = 1; off < 32; off <<= 1) {
            int n = __shfl_up_sync(0xffffffffu, bps, off);
            if (l2 >= off) bps += n;
        }
        if (l2 == bid) sh[8] = bps - bv;
        if (bid == SCAN_GRID - 1 && l2 == SCAN_GRID - 1)
            g_rowptr[N_NODES] = bps;
    }
    __syncthreads();
    int off = sh[8];
#pragma unroll
    for (int j = 0; j < 8; j++) {
        int i = base + j;
        if (i < N_NODES) g_rowptr[i] = local[j] + off;
    }

    // ---- reset barrier scratch: last block out cleans up ----
    __syncthreads();
    if (tid == 0) {
        int t = atomicAdd(&g_rowcnt[N_NODES + 1], 1);
        if (t == SCAN_GRID - 1) {
            g_rowcnt[N_NODES] = 0;
            g_rowcnt[N_NODES + 1] = 0;
            ((volatile int*)g_rowcnt)[N_NODES + 4] = 0;
        }
    }
}

// fill: no atomics — pos = rowptr[dst] + rank; 8 edges per thread for MLP
__global__ void fill_kernel(const int* __restrict__ src,
                            const int* __restrict__ dst) {
    int e8 = (blockIdx.x * blockDim.x + threadIdx.x) * 8;
    if (e8 < E_EDGES) {   // E_EDGES % 8 == 0
        int4 s0 = *reinterpret_cast<const int4*>(src + e8);
        int4 s1 = *reinterpret_cast<const int4*>(src + e8 + 4);
        int4 d0 = *reinterpret_cast<const int4*>(dst + e8);
        int4 d1 = *reinterpret_cast<const int4*>(dst + e8 + 4);
        int4 r0 = *reinterpret_cast<const int4*>(g_rank + e8);
        int4 r1 = *reinterpret_cast<const int4*>(g_rank + e8 + 4);
        int p0 = __ldg(&g_rowptr[d0.x]);
        int p1 = __ldg(&g_rowptr[d0.y]);
        int p2 = __ldg(&g_rowptr[d0.z]);
        int p3 = __ldg(&g_rowptr[d0.w]);
        int p4 = __ldg(&g_rowptr[d1.x]);
        int p5 = __ldg(&g_rowptr[d1.y]);
        int p6 = __ldg(&g_rowptr[d1.z]);
        int p7 = __ldg(&g_rowptr[d1.w]);
        g_csr_src[p0 + r0.x] = s0.x;
        g_csr_src[p1 + r0.y] = s0.y;
        g_csr_src[p2 + r0.z] = s0.z;
        g_csr_src[p3 + r0.w] = s0.w;
        g_csr_src[p4 + r1.x] = s1.x;
        g_csr_src[p5 + r1.y] = s1.y;
        g_csr_src[p6 + r1.z] = s1.z;
        g_csr_src[p7 + r1.w] = s1.w;
    }
}

// ---------------------------------------------------------------------------
// Gather layer 1 (fp32, 128 dims, warp per node) — 4x unrolled
// ---------------------------------------------------------------------------
__global__ void gather1_kernel(const float* __restrict__ x) {
    int node = (blockIdx.x * blockDim.x + threadIdx.x) >> 5;
    int lane = threadIdx.x & 31;
    if (node >= N_NODES) return;
    int beg = g_rowptr[node];
    int end = g_rowptr[node + 1];

    float4 acc = *reinterpret_cast<const float4*>(x + (size_t)node * D + lane * 4);

    for (int base = beg; base < end; base += 32) {
        int idx = 0;
        if (base + lane < end) idx = __ldg(&g_csr_src[base + lane]);
        int m = end - base; if (m > 32) m = 32;
        int j = 0;
        for (; j + 4 <= m; j += 4) {
            int s0 = __shfl_sync(0xffffffffu, idx, j);
            int s1 = __shfl_sync(0xffffffffu, idx, j + 1);
            int s2 = __shfl_sync(0xffffffffu, idx, j + 2);
            int s3 = __shfl_sync(0xffffffffu, idx, j + 3);
            float4 v0 = *reinterpret_cast<const float4*>(x + (size_t)s0 * D + lane * 4);
            float4 v1 = *reinterpret_cast<const float4*>(x + (size_t)s1 * D + lane * 4);
            float4 v2 = *reinterpret_cast<const float4*>(x + (size_t)s2 * D + lane * 4);
            float4 v3 = *reinterpret_cast<const float4*>(x + (size_t)s3 * D + lane * 4);
            acc.x += (v0.x + v1.x) + (v2.x + v3.x);
            acc.y += (v0.y + v1.y) + (v2.y + v3.y);
            acc.z += (v0.z + v1.z) + (v2.z + v3.z);
            acc.w += (v0.w + v1.w) + (v2.w + v3.w);
        }
        for (; j < m; j++) {
            int s = __shfl_sync(0xffffffffu, idx, j);
            float4 v = *reinterpret_cast<const float4*>(x + (size_t)s * D + lane * 4);
            acc.x += v.x; acc.y += v.y; acc.z += v.z; acc.w += v.w;
        }
    }
    float inv = 1.0f / (float)(end - beg + 1);
    acc.x *= inv; acc.y *= inv; acc.z *= inv; acc.w *= inv;
    *reinterpret_cast<float4*>(g_agg1 + (size_t)node * D + lane * 4) = acc;
}

// ---------------------------------------------------------------------------
// Fused GEMM via mma.sync tf32 (3xTF32 split), 512 threads / 128-row tile
// ---------------------------------------------------------------------------
#define ASTR 132
#define FG_SMEM ((D + 128 * ASTR + 2 * 128 * ASTR) * 4)

__global__ void __launch_bounds__(512, 1) fusedgemm_kernel() {
    extern __shared__ float sm[];
    float* bias = sm;
    float* sA   = sm + D;
    float* sWh  = sA + 128 * ASTR;
    float* sWl  = sWh + 128 * ASTR;

    int tid = threadIdx.x;
    int w = tid >> 5, lane = tid & 31;
    int g = lane >> 2, qi = lane & 3;
    int row0 = blockIdx.x * 128;

    if (tid < D) bias[tid] = g_bc[tid];
    for (int i = tid; i < 128 * 32; i += 512) {
        int r = i >> 5, c4 = (i & 31) << 2;
        float4 v = make_float4(0.f, 0.f, 0.f, 0.f);
        int row = row0 + r;
        if (row < N_NODES) v = *reinterpret_cast<const float4*>(g_agg1 + (size_t)row * D + c4);
        *reinterpret_cast<float4*>(&sA[r * ASTR + c4]) = v;
    }
    for (int i = tid; i < 128 * 32; i += 512) {
        int r = i >> 5, c4 = (i & 31) << 2;
        *reinterpret_cast<float4*>(&sWh[r * ASTR + c4]) =
            *reinterpret_cast<const float4*>(&g_WcT_h[r * D + c4]);
        *reinterpret_cast<float4*>(&sWl[r * ASTR + c4]) =
            *reinterpret_cast<const float4*>(&g_WcT_l[r * D + c4]);
    }
    __syncthreads();

    int rw0 = (w >> 2) * 32;
    int cw0 = (w & 3) * 32;
    float acc[2][4][4];
#pragma unroll
    for (int mt = 0; mt < 2; mt++)
#pragma unroll
        for (int nt = 0; nt < 4; nt++)
#pragma unroll
            for (int j = 0; j < 4; j++) acc[mt][nt][j] = 0.f;

#pragma unroll 4
    for (int ks = 0; ks < 16; ks++) {
        int k0 = ks * 8;
        uint32_t ah[2][4], al[2][4];
#pragma unroll
        for (int mt = 0; mt < 2; mt++) {
            int rb = rw0 + mt * 16;
            float f0 = sA[(rb + g) * ASTR + k0 + qi];
            float f1 = sA[(rb + g + 8) * ASTR + k0 + qi];
            float f2 = sA[(rb + g) * ASTR + k0 + qi + 4];
            float f3 = sA[(rb + g + 8) * ASTR + k0 + qi + 4];
            split_tf32(f0, ah[mt][0], al[mt][0]);
            split_tf32(f1, ah[mt][1], al[mt][1]);
            split_tf32(f2, ah[mt][2], al[mt][2]);
            split_tf32(f3, ah[mt][3], al[mt][3]);
        }
#pragma unroll
        for (int nt = 0; nt < 4; nt++) {
            int nb = cw0 + nt * 8;
            uint32_t bh0 = __float_as_uint(sWh[(nb + g) * ASTR + k0 + qi]);
            uint32_t bh1 = __float_as_uint(sWh[(nb + g) * ASTR + k0 + qi + 4]);
            uint32_t bl0 = __float_as_uint(sWl[(nb + g) * ASTR + k0 + qi]);
            uint32_t bl1 = __float_as_uint(sWl[(nb + g) * ASTR + k0 + qi + 4]);
#pragma unroll
            for (int mt = 0; mt < 2; mt++) {
                mma_tf32(acc[mt][nt], ah[mt], bh0, bh1);
                mma_tf32(acc[mt][nt], ah[mt], bl0, bl1);
                mma_tf32(acc[mt][nt], al[mt], bh0, bh1);
            }
        }
    }
    __syncthreads();

#pragma unroll
    for (int mt = 0; mt < 2; mt++) {
        int rb = rw0 + mt * 16;
#pragma unroll
        for (int nt = 0; nt < 4; nt++) {
            int c0 = cw0 + nt * 8 + qi * 2;
            float b0 = bias[c0], b1 = bias[c0 + 1];
            sA[(rb + g) * ASTR + c0]         = fmaxf(acc[mt][nt][0] + b0, 0.f);
            sA[(rb + g) * ASTR + c0 + 1]     = fmaxf(acc[mt][nt][1] + b1, 0.f);
            sA[(rb + g + 8) * ASTR + c0]     = fmaxf(acc[mt][nt][2] + b0, 0.f);
            sA[(rb + g + 8) * ASTR + c0 + 1] = fmaxf(acc[mt][nt][3] + b1, 0.f);
        }
    }
    __syncthreads();

    float* sW2h = sWh;
    float* sW2l = sWh + DOUT * ASTR;
    for (int i = tid; i < DOUT * 32; i += 512) {
        int r = i >> 5, c4 = (i & 31) << 2;
        *reinterpret_cast<float4*>(&sW2h[r * ASTR + c4]) =
            *reinterpret_cast<const float4*>(&g_W2T_h[r * D + c4]);
        *reinterpret_cast<float4*>(&sW2l[r * ASTR + c4]) =
            *reinterpret_cast<const float4*>(&g_W2T_l[r * D + c4]);
    }
    __syncthreads();

    int cw2 = (w & 3) * 16;
    float acc2[2][2][4];
#pragma unroll
    for (int mt = 0; mt < 2; mt++)
#pragma unroll
        for (int nt = 0; nt < 2; nt++)
#pragma unroll
            for (int j = 0; j < 4; j++) acc2[mt][nt][j] = 0.f;

#pragma unroll 4
    for (int ks = 0; ks < 16; ks++) {
        int k0 = ks * 8;
        uint32_t ah[2][4], al[2][4];
#pragma unroll
        for (int mt = 0; mt < 2; mt++) {
            int rb = rw0 + mt * 16;
            float f0 = sA[(rb + g) * ASTR + k0 + qi];
            float f1 = sA[(rb + g + 8) * ASTR + k0 + qi];
            float f2 = sA[(rb + g) * ASTR + k0 + qi + 4];
            float f3 = sA[(rb + g + 8) * ASTR + k0 + qi + 4];
            split_tf32(f0, ah[mt][0], al[mt][0]);
            split_tf32(f1, ah[mt][1], al[mt][1]);
            split_tf32(f2, ah[mt][2], al[mt][2]);
            split_tf32(f3, ah[mt][3], al[mt][3]);
        }
#pragma unroll
        for (int nt = 0; nt < 2; nt++) {
            int nb = cw2 + nt * 8;
            uint32_t bh0 = __float_as_uint(sW2h[(nb + g) * ASTR + k0 + qi]);
            uint32_t bh1 = __float_as_uint(sW2h[(nb + g) * ASTR + k0 + qi + 4]);
            uint32_t bl0 = __float_as_uint(sW2l[(nb + g) * ASTR + k0 + qi]);
            uint32_t bl1 = __float_as_uint(sW2l[(nb + g) * ASTR + k0 + qi + 4]);
#pragma unroll
            for (int mt = 0; mt < 2; mt++) {
                mma_tf32(acc2[mt][nt], ah[mt], bh0, bh1);
                mma_tf32(acc2[mt][nt], ah[mt], bl0, bl1);
                mma_tf32(acc2[mt][nt], al[mt], bh0, bh1);
            }
        }
    }
    __syncthreads();

    float* h2s = sA;
#pragma unroll
    for (int mt = 0; mt < 2; mt++) {
        int rb = rw0 + mt * 16;
#pragma unroll
        for (int nt = 0; nt < 2; nt++) {
            int c0 = cw2 + nt * 8 + qi * 2;
            h2s[(rb + g) * 66 + c0]         = acc2[mt][nt][0];
            h2s[(rb + g) * 66 + c0 + 1]     = acc2[mt][nt][1];
            h2s[(rb + g + 8) * 66 + c0]     = acc2[mt][nt][2];
            h2s[(rb + g + 8) * 66 + c0 + 1] = acc2[mt][nt][3];
        }
    }
    __syncthreads();
    for (int i = tid; i < 128 * 32; i += 512) {
        int r = i >> 5, c2 = (i & 31) << 1;
        int row = row0 + r;
        if (row < N_NODES) {
            float2 v = *reinterpret_cast<const float2*>(&h2s[r * 66 + c2]);
            *reinterpret_cast<float2*>(&g_h2[(size_t)row * DOUT + c2]) = v;
        }
    }
}

// ---------------------------------------------------------------------------
// Gather layer 2 + bias + L2 normalize: HALF-WARP per node, float4 lanes
// ---------------------------------------------------------------------------
__global__ void gather2_kernel(const float* __restrict__ b2,
                               float* __restrict__ out) {
    int gw = (blockIdx.x * blockDim.x + threadIdx.x) >> 5;
    int lane = threadIdx.x & 31;
    int half = lane >> 4, l = lane & 15;
    int node = gw * 2 + half;
    if (node >= N_NODES) return;
    unsigned hmask = 0xFFFFu << (half * 16);
    int sbase = half * 16;

    int beg = g_rowptr[node];
    int end = g_rowptr[node + 1];

    float4 acc = *reinterpret_cast<const float4*>(g_h2 + (size_t)node * DOUT + l * 4);

    for (int base = beg; base < end; base += 16) {
        int idx = 0;
        if (base + l < end) idx = __ldg(&g_csr_src[base + l]);
        int m = end - base; if (m > 16) m = 16;
        int j = 0;
        for (; j + 4 <= m; j += 4) {
            int s0 = __shfl_sync(hmask, idx, sbase + j);
            int s1 = __shfl_sync(hmask, idx, sbase + j + 1);
            int s2 = __shfl_sync(hmask, idx, sbase + j + 2);
            int s3 = __shfl_sync(hmask, idx, sbase + j + 3);
            float4 v0 = *reinterpret_cast<const float4*>(g_h2 + (size_t)s0 * DOUT + l * 4);
            float4 v1 = *reinterpret_cast<const float4*>(g_h2 + (size_t)s1 * DOUT + l * 4);
            float4 v2 = *reinterpret_cast<const float4*>(g_h2 + (size_t)s2 * DOUT + l * 4);
            float4 v3 = *reinterpret_cast<const float4*>(g_h2 + (size_t)s3 * DOUT + l * 4);
            acc.x += (v0.x + v1.x) + (v2.x + v3.x);
            acc.y += (v0.y + v1.y) + (v2.y + v3.y);
            acc.z += (v0.z + v1.z) + (v2.z + v3.z);
            acc.w += (v0.w + v1.w) + (v2.w + v3.w);
        }
        for (; j < m; j++) {
            int s = __shfl_sync(hmask, idx, sbase + j);
            float4 v = *reinterpret_cast<const float4*>(g_h2 + (size_t)s * DOUT + l * 4);
            acc.x += v.x; acc.y += v.y; acc.z += v.z; acc.w += v.w;
        }
    }
    float inv = 1.0f / (float)(end - beg + 1);
    float4 b = *reinterpret_cast<const float4*>(b2 + l * 4);
    float a0 = acc.x * inv + b.x;
    float a1 = acc.y * inv + b.y;
    float a2 = acc.z * inv + b.z;
    float a3 = acc.w * inv + b.w;
    float ss = a0 * a0 + a1 * a1 + a2 * a2 + a3 * a3;
#pragma unroll
    for (int o = 8; o; o >>= 1) ss += __shfl_xor_sync(hmask, ss, o);
    float s = 1.0f / fmaxf(sqrtf(ss), 1e-12f);
    float4 o4 = make_float4(a0 * s, a1 * s, a2 * s, a3 * s);
    *reinterpret_cast<float4*>(&out[(size_t)node * DOUT + l * 4]) = o4;
}

// ---------------------------------------------------------------------------
extern "C" void kernel_launch(void* const* d_in, const int* in_sizes, int n_in,
                              void* d_out, int out_size) {
    const float* x     = (const float*)d_in[0];
    const int*   ei    = (const int*)d_in[1];
    const float* W_pre = (const float*)d_in[2];
    const float* b_pre = (const float*)d_in[3];
    const float* W1    = (const float*)d_in[4];
    const float* b1    = (const float*)d_in[5];
    const float* W2    = (const float*)d_in[6];
    const float* b2    = (const float*)d_in[7];
    float* out = (float*)d_out;

    const int* src = ei;
    const int* dst = ei + E_EDGES;

    static bool attr_set = false;
    if (!attr_set) {
        cudaFuncSetAttribute(fusedgemm_kernel,
                             cudaFuncAttributeMaxDynamicSharedMemorySize, FG_SMEM);
        attr_set = true;
    }

    prephist_kernel<<<PH_BLOCKS, 256>>>(dst, W_pre, b_pre, W1, b1, W2);
    scan_kernel<<<SCAN_GRID, 256>>>();
    fill_kernel<<<(E_EDGES / 8 + 255) / 256, 256>>>(src, dst);
    gather1_kernel<<<(N_NODES * 32 + 255) / 256, 256>>>(x);
    fusedgemm_kernel<<<(N_NODES + 127) / 128, 512, FG_SMEM>>>();
    gather2_kernel<<<((N_NODES + 1) / 2 * 32 + 255) / 256, 256>>>(b2, out);
}